// round 7
// baseline (speedup 1.0000x reference)
#include <cuda_runtime.h>
#include <math.h>
#include <string.h>

#define TT 100
#define BB 64
#define II 256
#define HH 512
#define H3 1536
#define H4 2048
#define NBLK 128          // persistent grid (all co-resident; 128 < 148 SMs)

// B-tile float4-index permutation (bank spread)
#define PF4(x) ((x) + ((x) >> 3))

// ---------------- f32x2 helpers ----------------
__device__ __forceinline__ void ffma2(unsigned long long& d, unsigned long long a, unsigned long long b) {
    asm("fma.rn.f32x2 %0, %1, %2, %0;" : "+l"(d) : "l"(a), "l"(b));
}
__device__ __forceinline__ float2 u2f2(unsigned long long u) { float2 f; memcpy(&f, &u, 8); return f; }

// ---------------- scratch (device globals) ----------------
__device__ float g_WihP[II * H4];                 // packed: [k][ (hcol)*4 + gate ]
__device__ float g_biasP[H4];
__device__ float g_Gx[(size_t)TT * BB * H4];      // packed gate pre-acts (input path + bias)
__device__ float g_h[(size_t)(TT + 1) * BB * HH]; // h history [t][b][h]
__device__ float g_f[(size_t)TT * BB * HH];
__device__ float g_d[(size_t)TT * BB * H3];       // later overwritten with w = d * suffix-prod(f)
__device__ unsigned g_scnt[TT][16];               // per-step distributed barrier counters

// ---------------- prep ----------------
__global__ void prep_kernel(const float* __restrict__ h0, const float* __restrict__ bih,
                            const float* __restrict__ bhh) {
    int i = blockIdx.x * blockDim.x + threadIdx.x;
    if (i < TT * 16) (&g_scnt[0][0])[i] = 0u;
    if (i < H4) g_biasP[(i & 511) * 4 + (i >> 9)] = bih[i] + bhh[i];
    if (i < BB * HH) g_h[i] = h0[i];
}

// ---------------- pack W_ih: in[2048][256] -> [k][packed n] ----------------
__global__ void pack_w(const float* __restrict__ in) {
    __shared__ float s[32][33];
    int k0 = blockIdx.x * 32, n0 = blockIdx.y * 32;
    int tx = threadIdx.x, ty = threadIdx.y;
    for (int i = ty; i < 32; i += 8)
        s[i][tx] = in[(size_t)(n0 + i) * II + k0 + tx];
    __syncthreads();
    int g = n0 >> 9;
    int c = n0 & 511;
    for (int i = ty; i < 32; i += 8)
        g_WihP[(size_t)(k0 + i) * H4 + (c + tx) * 4 + g] = s[tx][i];
}

// ---------------- Gx = X[6400,256] @ WihP + biasP (packed out), FFMA2 ----------------
// 128x128 tile, 256 threads, 8x8 microtile, BK=8. B pre-duplicated in smem.
__global__ void __launch_bounds__(256, 2) gx_kernel(const float* __restrict__ X) {
    __shared__ __align__(16) float As[8][132];
    __shared__ __align__(16) float Bsd[8][288];   // 72 f4 slots (dup pairs), PF4 max 70
    const int tid = threadIdx.x;
    const int n0 = blockIdx.x * 128;
    const int m0 = blockIdx.y * 128;
    const int tm = (tid >> 4) * 8, tn = (tid & 15) * 8;
    const int am = tid >> 1, ak = (tid & 1) * 4;
    const int bk = tid >> 5, bc = tid & 31;       // staging f4 col
    const int s0 = tn >> 1;                       // dup f4 base slot
    unsigned long long acc2[4][8];
#pragma unroll
    for (int i = 0; i < 4; i++)
#pragma unroll
        for (int j = 0; j < 8; j++) acc2[i][j] = 0ull;
    for (int k0 = 0; k0 < II; k0 += 8) {
        float4 av = *(const float4*)(X + (size_t)(m0 + am) * II + k0 + ak);
        As[ak + 0][am] = av.x; As[ak + 1][am] = av.y; As[ak + 2][am] = av.z; As[ak + 3][am] = av.w;
        float4 xv = *(const float4*)(g_WihP + (size_t)(k0 + bk) * H4 + n0 + bc * 4);
        ((float4*)&Bsd[bk][0])[PF4(2 * bc)]     = make_float4(xv.x, xv.x, xv.y, xv.y);
        ((float4*)&Bsd[bk][0])[PF4(2 * bc + 1)] = make_float4(xv.z, xv.z, xv.w, xv.w);
        __syncthreads();
#pragma unroll
        for (int u = 0; u < 8; u++) {
            const unsigned long long* ap = (const unsigned long long*)&As[u][tm];
            unsigned long long a2[4] = {ap[0], ap[1], ap[2], ap[3]};
            unsigned long long b2[8];
#pragma unroll
            for (int s = 0; s < 4; s++) {
                float4 bv = ((const float4*)&Bsd[u][0])[PF4(s0 + s)];
                memcpy(&b2[2 * s], &bv.x, 8);
                memcpy(&b2[2 * s + 1], &bv.z, 8);
            }
#pragma unroll
            for (int i = 0; i < 4; i++)
#pragma unroll
                for (int j = 0; j < 8; j++)
                    ffma2(acc2[i][j], a2[i], b2[j]);
        }
        __syncthreads();
    }
#pragma unroll
    for (int i2 = 0; i2 < 4; i2++) {
        float r0[8], r1[8];
#pragma unroll
        for (int j = 0; j < 8; j++) {
            float2 v = u2f2(acc2[i2][j]);
            r0[j] = v.x + g_biasP[n0 + tn + j];
            r1[j] = v.y + g_biasP[n0 + tn + j];
        }
        float* o0 = g_Gx + (size_t)(m0 + tm + 2 * i2) * H4 + n0 + tn;
        float* o1 = o0 + H4;
        *(float4*)o0 = make_float4(r0[0], r0[1], r0[2], r0[3]);
        *(float4*)(o0 + 4) = make_float4(r0[4], r0[5], r0[6], r0[7]);
        *(float4*)o1 = make_float4(r1[0], r1[1], r1[2], r1[3]);
        *(float4*)(o1 + 4) = make_float4(r1[4], r1[5], r1[6], r1[7]);
    }
}

// ---------------- persistent recurrent loop ----------------
// 128 blocks x 256 threads. Block owns 4 h-cols (16 packed cols), full K=512.
// Weights dup-cached in smem (64KB). h staged per 64-k chunk with LDG prefetch.
// Cell fused via smem gate exchange; c-state in registers. One barrier per step.
__global__ void __launch_bounds__(256, 1)
loop_kernel(const float* __restrict__ whh, const float* __restrict__ c0,
            float* __restrict__ out_h, float* __restrict__ out_c) {
    extern __shared__ float sm[];
    float* Bsd = sm;                 // [512][32] dup  (65536 B)
    float* AsB = sm + 512 * 32;      // [64][64]       (16384 B)
    float* Gex = AsB + 64 * 64;      // [16][66]       (4224 B)

    const int tid = threadIdx.x;
    const int blk = blockIdx.x;
    const int hc0 = blk * 4;         // global h-col base

    // ---- stage dup weights: Bsd[k][2c..2c+2) = dup(whh[row(c)][k]) ----
    {
        const int c = tid & 15;
        const int kq = tid >> 4;                     // 0..15
        const int row = (c & 3) * HH + hc0 + (c >> 2);
        const float* wr = whh + (size_t)row * HH;
#pragma unroll
        for (int r = 0; r < 8; r++) {
            int kk = (kq + 16 * r) * 4;
            float4 xv = *(const float4*)(wr + kk);
            *(float2*)(Bsd + (size_t)(kk + 0) * 32 + 2 * c) = make_float2(xv.x, xv.x);
            *(float2*)(Bsd + (size_t)(kk + 1) * 32 + 2 * c) = make_float2(xv.y, xv.y);
            *(float2*)(Bsd + (size_t)(kk + 2) * 32 + 2 * c) = make_float2(xv.z, xv.z);
            *(float2*)(Bsd + (size_t)(kk + 3) * 32 + 2 * c) = make_float2(xv.w, xv.w);
        }
    }

    // GEMM thread identity: m-pair + q (2 local cols)
    const int mp = tid & 31;                // m0 = 2mp, m1 = 2mp+1
    const int q  = tid >> 5;                // 0..7 -> local cols 2q, 2q+1
    // A staging identity
    const int sm_m = tid & 63, sm_kq = tid >> 6;    // kq 0..3
    // cell identity
    const int cm = tid & 63, cq = tid >> 6;         // batch, local h-col (0..3)
    float creg = c0[(size_t)cm * HH + hc0 + cq];

    __syncthreads();

    for (int t = 0; t < TT; t++) {
        // ---- wait for h[t] (skip t=0) ----
        if (t > 0) {
            if (tid < 32) {
                volatile unsigned* p = &g_scnt[t - 1][tid & 15];
                for (;;) {
                    unsigned v = (tid < 16) ? *p : 8u;
                    if (__all_sync(0xffffffffu, v >= 8u)) break;
                    __nanosleep(64);
                }
                __threadfence();
            }
            __syncthreads();
        }

        const float* hsrc = g_h + (size_t)t * BB * HH;
        unsigned long long acc2[2] = {0ull, 0ull};

        // prefetch chunk 0
        float4 pf[4];
#pragma unroll
        for (int r = 0; r < 4; r++)
            pf[r] = __ldcg((const float4*)(hsrc + (size_t)sm_m * HH + (sm_kq + 4 * r) * 4));

        for (int ch = 0; ch < 8; ch++) {
            __syncthreads();   // AsB free
#pragma unroll
            for (int r = 0; r < 4; r++) {
                int kk = (sm_kq + 4 * r) * 4;
                AsB[(size_t)(kk + 0) * 64 + sm_m] = pf[r].x;
                AsB[(size_t)(kk + 1) * 64 + sm_m] = pf[r].y;
                AsB[(size_t)(kk + 2) * 64 + sm_m] = pf[r].z;
                AsB[(size_t)(kk + 3) * 64 + sm_m] = pf[r].w;
            }
            __syncthreads();
            if (ch < 7) {
#pragma unroll
                for (int r = 0; r < 4; r++)
                    pf[r] = __ldcg((const float4*)(hsrc + (size_t)sm_m * HH + (ch + 1) * 64 + (sm_kq + 4 * r) * 4));
            }
            const float* brow = Bsd + (size_t)ch * 64 * 32;
#pragma unroll 8
            for (int k = 0; k < 64; k++) {
                unsigned long long a2 = *(const unsigned long long*)(AsB + (size_t)k * 64 + 2 * mp);
                float4 bv = ((const float4*)(brow + (size_t)k * 32))[q];
                unsigned long long b0, b1;
                memcpy(&b0, &bv.x, 8);
                memcpy(&b1, &bv.z, 8);
                ffma2(acc2[0], a2, b0);
                ffma2(acc2[1], a2, b1);
            }
        }

        // ---- gate exchange ----
        *(float2*)(Gex + (size_t)(2 * q) * 66 + 2 * mp)     = u2f2(acc2[0]);
        *(float2*)(Gex + (size_t)(2 * q + 1) * 66 + 2 * mp) = u2f2(acc2[1]);
        __syncthreads();

        // ---- fused cell ----
        {
            float4 g4 = __ldcg((const float4*)(g_Gx + ((size_t)t * BB + cm) * H4 + 4 * (hc0 + cq)));
            g4.x += Gex[(size_t)(4 * cq + 0) * 66 + cm];
            g4.y += Gex[(size_t)(4 * cq + 1) * 66 + cm];
            g4.z += Gex[(size_t)(4 * cq + 2) * 66 + cm];
            g4.w += Gex[(size_t)(4 * cq + 3) * 66 + cm];
            float i = 1.f / (1.f + expf(-g4.x));
            float f = 1.f / (1.f + expf(-g4.y));
            float g = tanhf(g4.z);
            float o = 1.f / (1.f + expf(-g4.w));
            float cx = creg;
            float cy = f * cx + i * g;
            float hy = o * tanhf(cy);
            creg = cy;
            size_t hb = (size_t)cm * HH + hc0 + cq;
            g_h[(size_t)(t + 1) * BB * HH + hb] = hy;
            out_h[(size_t)t * BB * HH + hb] = hy;
            g_f[(size_t)t * BB * HH + hb] = f;
            size_t db = (size_t)t * BB * H3 + (size_t)cm * H3 + hc0 + cq;
            g_d[db]          = g * i * (1.f - i);
            g_d[db + HH]     = cx * f * (1.f - f);
            g_d[db + 2 * HH] = i * (1.f - g) * (1.f + g);
            if (t == TT - 1) out_c[hb] = cy;
        }

        // ---- arrive ----
        __threadfence();
        __syncthreads();
        if (tid == 0) atomicAdd(&g_scnt[t][blk & 15], 1u);
    }
}

// ---------------- reverse suffix-product scan ----------------
__global__ void scan_kernel(float* __restrict__ evb_out) {
    int idx = blockIdx.x * blockDim.x + threadIdx.x;  // < BB*H3
    int b = idx / H3, j = idx % H3;
    int h = j & (HH - 1);
    float p = 1.f, sum = 0.f;
    for (int t = TT - 1; t >= 0; t--) {
        size_t di = (size_t)t * BB * H3 + (size_t)b * H3 + j;
        float w = g_d[di] * p;
        g_d[di] = w;
        sum += w;
        p *= g_f[(size_t)t * BB * HH + (size_t)b * HH + h];
    }
    evb_out[idx] = sum;
}

// ---------------- batched ev GEMM (FFMA2): out[b][j][k] = sum_t w[t][b][j] * Xs[t][b][k] ----------------
__global__ void __launch_bounds__(256, 2)
ev_kernel(const float* __restrict__ Xs, int kdim, float* __restrict__ out) {
    __shared__ __align__(16) float Ws[8][132];
    __shared__ __align__(16) float Bsd[8][288];
    if (Xs == nullptr) Xs = g_h;  // ev_hh: h_{t-1} history
    const int tid = threadIdx.x;
    const int b = blockIdx.z;
    const int j0 = blockIdx.y * 128;
    const int k0 = blockIdx.x * 128;
    const int tj = (tid >> 4) * 8, tk = (tid & 15) * 8;
    const int s0 = tk >> 1;
    const int ltt = tid >> 5;
    const int lc = tid & 31;
    unsigned long long acc2[4][8];
#pragma unroll
    for (int i = 0; i < 4; i++)
#pragma unroll
        for (int j = 0; j < 8; j++) acc2[i][j] = 0ull;
    for (int t0 = 0; t0 < TT; t0 += 8) {
        int t = t0 + ltt;
        float4 wv = make_float4(0.f, 0.f, 0.f, 0.f);
        float4 xv = make_float4(0.f, 0.f, 0.f, 0.f);
        if (t < TT) {
            wv = *(const float4*)(g_d + (size_t)t * BB * H3 + (size_t)b * H3 + j0 + lc * 4);
            xv = *(const float4*)(Xs + ((size_t)t * BB + b) * kdim + k0 + lc * 4);
        }
        *(float4*)&Ws[ltt][lc * 4] = wv;
        ((float4*)&Bsd[ltt][0])[PF4(2 * lc)]     = make_float4(xv.x, xv.x, xv.y, xv.y);
        ((float4*)&Bsd[ltt][0])[PF4(2 * lc + 1)] = make_float4(xv.z, xv.z, xv.w, xv.w);
        __syncthreads();
#pragma unroll
        for (int u = 0; u < 8; u++) {
            const unsigned long long* ap = (const unsigned long long*)&Ws[u][tj];
            unsigned long long a2[4] = {ap[0], ap[1], ap[2], ap[3]};
            unsigned long long b2[8];
#pragma unroll
            for (int s = 0; s < 4; s++) {
                float4 bv = ((const float4*)&Bsd[u][0])[PF4(s0 + s)];
                memcpy(&b2[2 * s], &bv.x, 8);
                memcpy(&b2[2 * s + 1], &bv.z, 8);
            }
#pragma unroll
            for (int i = 0; i < 4; i++)
#pragma unroll
                for (int j = 0; j < 8; j++)
                    ffma2(acc2[i][j], a2[i], b2[j]);
        }
        __syncthreads();
    }
#pragma unroll
    for (int i2 = 0; i2 < 4; i2++) {
        float r0[8], r1[8];
#pragma unroll
        for (int j = 0; j < 8; j++) {
            float2 v = u2f2(acc2[i2][j]);
            r0[j] = v.x; r1[j] = v.y;
        }
        float* o0 = out + ((size_t)b * H3 + j0 + tj + 2 * i2) * kdim + k0 + tk;
        float* o1 = o0 + kdim;
        *(float4*)o0 = make_float4(r0[0], r0[1], r0[2], r0[3]);
        *(float4*)(o0 + 4) = make_float4(r0[4], r0[5], r0[6], r0[7]);
        *(float4*)o1 = make_float4(r1[0], r1[1], r1[2], r1[3]);
        *(float4*)(o1 + 4) = make_float4(r1[4], r1[5], r1[6], r1[7]);
    }
}

// ---------------- launch ----------------
extern "C" void kernel_launch(void* const* d_in, const int* in_sizes, int n_in,
                              void* d_out, int out_size) {
    (void)in_sizes; (void)n_in; (void)out_size;
    const float* input = (const float*)d_in[0];
    const float* h0    = (const float*)d_in[1];
    const float* c0    = (const float*)d_in[2];
    const float* wih   = (const float*)d_in[3];
    const float* whh   = (const float*)d_in[4];
    const float* bih   = (const float*)d_in[5];
    const float* bhh   = (const float*)d_in[6];

    float* out         = (float*)d_out;
    float* out_outputs = out;
    float* out_cx      = out_outputs + (size_t)TT * BB * HH;
    float* out_evih    = out_cx + (size_t)BB * HH;
    float* out_evhh    = out_evih + (size_t)BB * H3 * II;
    float* out_evb     = out_evhh + (size_t)BB * H3 * HH;

    const int loop_smem = (512 * 32 + 64 * 64 + 16 * 66) * 4;   // ~86 KB
    cudaFuncSetAttribute(loop_kernel, cudaFuncAttributeMaxDynamicSharedMemorySize, loop_smem);

    prep_kernel<<<512, 256>>>(h0, bih, bhh);
    pack_w<<<dim3(II / 32, H4 / 32), dim3(32, 8)>>>(wih);
    gx_kernel<<<dim3(16, 50), 256>>>(input);

    loop_kernel<<<NBLK, 256, loop_smem>>>(whh, c0, out_outputs, out_cx);

    scan_kernel<<<BB * H3 / 256, 256>>>(out_evb);
    ev_kernel<<<dim3(II / 128, H3 / 128, BB), 256>>>(input, II, out_evih);
    ev_kernel<<<dim3(HH / 128, H3 / 128, BB), 256>>>(nullptr, HH, out_evhh);
}

// round 8
// speedup vs baseline: 1.5697x; 1.5697x over previous
#include <cuda_runtime.h>
#include <math.h>
#include <string.h>

#define TT 100
#define BB 64
#define II 256
#define HH 512
#define H3 1536
#define H4 2048
#define NBLK 128          // persistent grid size (all co-resident)
#define KC 16             // K split chunks across blocks (512/32)
#define BKC 32            // K per chunk

// B-tile float4-index permutation: spreads lane-stride-8-word reads over all banks
#define PF4(x) ((x) + ((x) >> 3))

// ---------------- f32x2 helpers ----------------
__device__ __forceinline__ void ffma2(unsigned long long& d, unsigned long long a, unsigned long long b) {
    asm("fma.rn.f32x2 %0, %1, %2, %0;" : "+l"(d) : "l"(a), "l"(b));
}
__device__ __forceinline__ float2 u2f2(unsigned long long u) { float2 f; memcpy(&f, &u, 8); return f; }

// ---------------- scratch (device globals) ----------------
__device__ float g_WihP[II * H4];                 // packed: [k][ (n%512)*4 + n/512 ]
__device__ float g_WhhP[HH * H4];
__device__ float g_biasP[H4];
__device__ float g_Gx[(size_t)TT * BB * H4];      // packed gate pre-activations from input path
__device__ float g_h[(size_t)(TT + 1) * BB * HH]; // h history [t][b][h]
__device__ float g_f[(size_t)TT * BB * HH];
__device__ float g_d[(size_t)TT * BB * H3];       // later overwritten with w = d * suffix-prod(f)
__device__ float g_gpart[(size_t)KC * BB * H4];   // split-K partials, packed cols
__device__ unsigned g_cnt_g[TT][8];               // partials-done counters per (t, nt)
__device__ unsigned g_cnt_c[TT][8];               // cells-done counters per (t, nt)

// ---------------- prep ----------------
__global__ void prep_kernel(const float* __restrict__ h0, const float* __restrict__ bih,
                            const float* __restrict__ bhh) {
    int i = blockIdx.x * blockDim.x + threadIdx.x;
    if (i < TT * 8) { (&g_cnt_g[0][0])[i] = 0u; (&g_cnt_c[0][0])[i] = 0u; }
    if (i < H4) g_biasP[(i & 511) * 4 + (i >> 9)] = bih[i] + bhh[i];
    if (i < BB * HH) g_h[i] = h0[i];
}

// ---------------- pack weights: in[2048][K] -> out[K][2048 packed] ----------------
__global__ void pack_w(const float* __restrict__ in, int K, int which) {
    __shared__ float s[32][33];
    int k0 = blockIdx.x * 32, n0 = blockIdx.y * 32;
    int tx = threadIdx.x, ty = threadIdx.y;
    for (int i = ty; i < 32; i += 8)
        s[i][tx] = in[(size_t)(n0 + i) * K + k0 + tx];
    __syncthreads();
    float* out = which ? g_WhhP : g_WihP;
    int g = n0 >> 9;
    int c = n0 & 511;
    for (int i = ty; i < 32; i += 8)
        out[(size_t)(k0 + i) * H4 + (c + tx) * 4 + g] = s[tx][i];
}

// ---------------- Gx = X[6400,256] @ WihP + biasP (packed out), FFMA2 ----------------
// 128x128 tile, 256 threads, 8x8 microtile (4 m-pairs x 8 n), BK=8. B pre-duplicated in smem.
__global__ void __launch_bounds__(256, 2) gx_kernel(const float* __restrict__ X) {
    __shared__ __align__(16) float As[8][132];
    __shared__ __align__(16) float Bsd[8][288];   // 72 f4 slots (dup pairs), PF4 max 70
    const int tid = threadIdx.x;
    const int n0 = blockIdx.x * 128;
    const int m0 = blockIdx.y * 128;
    const int tm = (tid >> 4) * 8, tn = (tid & 15) * 8;
    const int am = tid >> 1, ak = (tid & 1) * 4;
    const int bk = tid >> 5, bc = tid & 31;       // staging f4 col
    const int s0 = tn >> 1;                       // dup f4 base slot
    unsigned long long acc2[4][8];
#pragma unroll
    for (int i = 0; i < 4; i++)
#pragma unroll
        for (int j = 0; j < 8; j++) acc2[i][j] = 0ull;
    for (int k0 = 0; k0 < II; k0 += 8) {
        float4 av = *(const float4*)(X + (size_t)(m0 + am) * II + k0 + ak);
        As[ak + 0][am] = av.x; As[ak + 1][am] = av.y; As[ak + 2][am] = av.z; As[ak + 3][am] = av.w;
        float4 xv = *(const float4*)(g_WihP + (size_t)(k0 + bk) * H4 + n0 + bc * 4);
        ((float4*)&Bsd[bk][0])[PF4(2 * bc)]     = make_float4(xv.x, xv.x, xv.y, xv.y);
        ((float4*)&Bsd[bk][0])[PF4(2 * bc + 1)] = make_float4(xv.z, xv.z, xv.w, xv.w);
        __syncthreads();
#pragma unroll
        for (int u = 0; u < 8; u++) {
            const unsigned long long* ap = (const unsigned long long*)&As[u][tm];
            unsigned long long a2[4] = {ap[0], ap[1], ap[2], ap[3]};
            unsigned long long b2[8];
#pragma unroll
            for (int s = 0; s < 4; s++) {
                float4 bv = ((const float4*)&Bsd[u][0])[PF4(s0 + s)];
                memcpy(&b2[2 * s], &bv.x, 8);
                memcpy(&b2[2 * s + 1], &bv.z, 8);
            }
#pragma unroll
            for (int i = 0; i < 4; i++)
#pragma unroll
                for (int j = 0; j < 8; j++)
                    ffma2(acc2[i][j], a2[i], b2[j]);
        }
        __syncthreads();
    }
#pragma unroll
    for (int i2 = 0; i2 < 4; i2++) {
        float r0[8], r1[8];
#pragma unroll
        for (int j = 0; j < 8; j++) {
            float2 v = u2f2(acc2[i2][j]);
            r0[j] = v.x + g_biasP[n0 + tn + j];
            r1[j] = v.y + g_biasP[n0 + tn + j];
        }
        float* o0 = g_Gx + (size_t)(m0 + tm + 2 * i2) * H4 + n0 + tn;
        float* o1 = o0 + H4;
        *(float4*)o0 = make_float4(r0[0], r0[1], r0[2], r0[3]);
        *(float4*)(o0 + 4) = make_float4(r0[4], r0[5], r0[6], r0[7]);
        *(float4*)o1 = make_float4(r1[0], r1[1], r1[2], r1[3]);
        *(float4*)(o1 + 4) = make_float4(r1[4], r1[5], r1[6], r1[7]);
    }
}

// ---------------- persistent recurrent loop: flag-pipelined split-K (R6 proven design) ----------------
// 128 blocks x 256 threads. Block (nt 0..7, kc 0..15): GEMM tile M=64,N=256(packed),K=32.
// Cell: block handles b in [kc*4, kc*4+4) x h-cols [nt*64, nt*64+64); c state in register.
__global__ void __launch_bounds__(256, 1)
loop_kernel(const float* __restrict__ c0, float* __restrict__ out_h, float* __restrict__ out_c) {
    __shared__ __align__(16) float Bs[BKC][284];   // 71 f4 slots (PF4 max 70)
    __shared__ __align__(16) float As[BKC][68];
    const int tid = threadIdx.x;
    const int nt = blockIdx.x & 7;
    const int kc = blockIdx.x >> 3;
    const int n0 = nt * 256;
    const int k0 = kc * BKC;

    // stage weight chunk once (swizzled)
    {
        const float* wsrc = g_WhhP + (size_t)k0 * H4 + n0;
#pragma unroll
        for (int r = 0; r < 8; r++) {
            int e = r * 256 + tid;
            int kk = e >> 6;
            int nf4 = e & 63;
            ((float4*)&Bs[kk][0])[PF4(nf4)] = *(const float4*)(wsrc + (size_t)kk * H4 + nf4 * 4);
        }
    }

    const int ttm = (tid >> 5) * 8;          // warp-uniform m (broadcast A reads)
    const int ttn = (tid & 31) * 8;
    const int pn0 = PF4(ttn >> 2);
    const int pn1 = PF4((ttn >> 2) + 1);
    const int am = tid >> 2, ak = (tid & 3) * 8;

    // cell identity (fixed all steps)
    const int cb = kc * 4 + (tid >> 6);      // batch
    const int chl = tid & 63;                // local h col
    const int ch = nt * 64 + chl;            // global h col
    float creg = c0[(size_t)cb * HH + ch];

    const int nt_src = kc >> 1;              // producer nt of this block's A k-chunk

    for (int t = 0; t < TT; t++) {
        // ---- wait for h[t] producers (skip t=0: prep wrote it) ----
        if (t > 0) {
            if (tid == 0) {
                volatile unsigned* p = &g_cnt_c[t - 1][nt_src];
                while (*p < 16u) __nanosleep(64);
                __threadfence();
            }
            __syncthreads();
        }

        // ---- load A chunk: h[t][64][k0..k0+32) -> As[k][m] ----
        const float* hsrc = g_h + (size_t)t * BB * HH;
        float4 v0 = __ldcg((const float4*)(hsrc + (size_t)am * HH + k0 + ak));
        float4 v1 = __ldcg((const float4*)(hsrc + (size_t)am * HH + k0 + ak + 4));
        As[ak + 0][am] = v0.x; As[ak + 1][am] = v0.y; As[ak + 2][am] = v0.z; As[ak + 3][am] = v0.w;
        As[ak + 4][am] = v1.x; As[ak + 5][am] = v1.y; As[ak + 6][am] = v1.z; As[ak + 7][am] = v1.w;
        __syncthreads();

        // ---- GEMM 64x256, K=32 ----
        float acc[8][8] = {};
#pragma unroll
        for (int u = 0; u < BKC; u++) {
            float4 a0 = *(const float4*)&As[u][ttm];
            float4 a1 = *(const float4*)&As[u][ttm + 4];
            float4 b0 = ((const float4*)&Bs[u][0])[pn0];
            float4 b1 = ((const float4*)&Bs[u][0])[pn1];
            float aa[8] = {a0.x, a0.y, a0.z, a0.w, a1.x, a1.y, a1.z, a1.w};
            float bb[8] = {b0.x, b0.y, b0.z, b0.w, b1.x, b1.y, b1.z, b1.w};
#pragma unroll
            for (int i = 0; i < 8; i++)
#pragma unroll
                for (int j = 0; j < 8; j++)
                    acc[i][j] += aa[i] * bb[j];
        }
#pragma unroll
        for (int i = 0; i < 8; i++) {
            float* prow = g_gpart + ((size_t)kc * BB + ttm + i) * H4 + n0 + ttn;
            *(float4*)prow = make_float4(acc[i][0], acc[i][1], acc[i][2], acc[i][3]);
            *(float4*)(prow + 4) = make_float4(acc[i][4], acc[i][5], acc[i][6], acc[i][7]);
        }

        // ---- signal partials done, wait for all 16 kc partials of our nt ----
        __threadfence();
        __syncthreads();                      // As also reused next step
        if (tid == 0) {
            atomicAdd(&g_cnt_g[t][nt], 1u);
            volatile unsigned* p = &g_cnt_g[t][nt];
            while (*p < 16u) __nanosleep(64);
            __threadfence();
        }
        __syncthreads();

        // ---- cell for (cb, ch) ----
        {
            float4 g4 = __ldcg((const float4*)(g_Gx + ((size_t)t * BB + cb) * H4 + 4 * ch));
#pragma unroll
            for (int q = 0; q < KC; q++) {
                float4 p = __ldcg((const float4*)(g_gpart + ((size_t)q * BB + cb) * H4 + 4 * ch));
                g4.x += p.x; g4.y += p.y; g4.z += p.z; g4.w += p.w;
            }
            float i = 1.f / (1.f + expf(-g4.x));
            float f = 1.f / (1.f + expf(-g4.y));
            float g = tanhf(g4.z);
            float o = 1.f / (1.f + expf(-g4.w));
            float cx = creg;
            float cy = f * cx + i * g;
            float hy = o * tanhf(cy);
            creg = cy;
            size_t hb = (size_t)cb * HH + ch;
            g_h[(size_t)(t + 1) * BB * HH + hb] = hy;
            out_h[(size_t)t * BB * HH + hb] = hy;
            g_f[(size_t)t * BB * HH + hb] = f;
            size_t db = (size_t)t * BB * H3 + (size_t)cb * H3 + ch;
            g_d[db]          = g * i * (1.f - i);
            g_d[db + HH]     = cx * f * (1.f - f);
            g_d[db + 2 * HH] = i * (1.f - g) * (1.f + g);
            if (t == TT - 1) out_c[hb] = cy;
        }

        // ---- signal cells done ----
        __threadfence();
        __syncthreads();
        if (tid == 0) atomicAdd(&g_cnt_c[t][nt], 1u);
    }
}

// ---------------- reverse suffix-product scan ----------------
__global__ void scan_kernel(float* __restrict__ evb_out) {
    int idx = blockIdx.x * blockDim.x + threadIdx.x;  // < BB*H3
    int b = idx / H3, j = idx % H3;
    int h = j & (HH - 1);
    float p = 1.f, sum = 0.f;
    for (int t = TT - 1; t >= 0; t--) {
        size_t di = (size_t)t * BB * H3 + (size_t)b * H3 + j;
        float w = g_d[di] * p;
        g_d[di] = w;
        sum += w;
        p *= g_f[(size_t)t * BB * HH + (size_t)b * HH + h];
    }
    evb_out[idx] = sum;
}

// ---------------- batched ev GEMM (FFMA2): out[b][j][k] = sum_t w[t][b][j] * Xs[t][b][k] ----------------
__global__ void __launch_bounds__(256, 2)
ev_kernel(const float* __restrict__ Xs, int kdim, float* __restrict__ out) {
    __shared__ __align__(16) float Ws[8][132];
    __shared__ __align__(16) float Bsd[8][288];
    if (Xs == nullptr) Xs = g_h;  // ev_hh: h_{t-1} history
    const int tid = threadIdx.x;
    const int b = blockIdx.z;
    const int j0 = blockIdx.y * 128;
    const int k0 = blockIdx.x * 128;
    const int tj = (tid >> 4) * 8, tk = (tid & 15) * 8;
    const int s0 = tk >> 1;
    const int ltt = tid >> 5;
    const int lc = tid & 31;
    unsigned long long acc2[4][8];
#pragma unroll
    for (int i = 0; i < 4; i++)
#pragma unroll
        for (int j = 0; j < 8; j++) acc2[i][j] = 0ull;
    for (int t0 = 0; t0 < TT; t0 += 8) {
        int t = t0 + ltt;
        float4 wv = make_float4(0.f, 0.f, 0.f, 0.f);
        float4 xv = make_float4(0.f, 0.f, 0.f, 0.f);
        if (t < TT) {
            wv = *(const float4*)(g_d + (size_t)t * BB * H3 + (size_t)b * H3 + j0 + lc * 4);
            xv = *(const float4*)(Xs + ((size_t)t * BB + b) * kdim + k0 + lc * 4);
        }
        *(float4*)&Ws[ltt][lc * 4] = wv;
        ((float4*)&Bsd[ltt][0])[PF4(2 * lc)]     = make_float4(xv.x, xv.x, xv.y, xv.y);
        ((float4*)&Bsd[ltt][0])[PF4(2 * lc + 1)] = make_float4(xv.z, xv.z, xv.w, xv.w);
        __syncthreads();
#pragma unroll
        for (int u = 0; u < 8; u++) {
            const unsigned long long* ap = (const unsigned long long*)&Ws[u][tj];
            unsigned long long a2[4] = {ap[0], ap[1], ap[2], ap[3]};
            unsigned long long b2[8];
#pragma unroll
            for (int s = 0; s < 4; s++) {
                float4 bv = ((const float4*)&Bsd[u][0])[PF4(s0 + s)];
                memcpy(&b2[2 * s], &bv.x, 8);
                memcpy(&b2[2 * s + 1], &bv.z, 8);
            }
#pragma unroll
            for (int i = 0; i < 4; i++)
#pragma unroll
                for (int j = 0; j < 8; j++)
                    ffma2(acc2[i][j], a2[i], b2[j]);
        }
        __syncthreads();
    }
#pragma unroll
    for (int i2 = 0; i2 < 4; i2++) {
        float r0[8], r1[8];
#pragma unroll
        for (int j = 0; j < 8; j++) {
            float2 v = u2f2(acc2[i2][j]);
            r0[j] = v.x; r1[j] = v.y;
        }
        float* o0 = out + ((size_t)b * H3 + j0 + tj + 2 * i2) * kdim + k0 + tk;
        float* o1 = o0 + kdim;
        *(float4*)o0 = make_float4(r0[0], r0[1], r0[2], r0[3]);
        *(float4*)(o0 + 4) = make_float4(r0[4], r0[5], r0[6], r0[7]);
        *(float4*)o1 = make_float4(r1[0], r1[1], r1[2], r1[3]);
        *(float4*)(o1 + 4) = make_float4(r1[4], r1[5], r1[6], r1[7]);
    }
}

// ---------------- launch ----------------
extern "C" void kernel_launch(void* const* d_in, const int* in_sizes, int n_in,
                              void* d_out, int out_size) {
    (void)in_sizes; (void)n_in; (void)out_size;
    const float* input = (const float*)d_in[0];
    const float* h0    = (const float*)d_in[1];
    const float* c0    = (const float*)d_in[2];
    const float* wih   = (const float*)d_in[3];
    const float* whh   = (const float*)d_in[4];
    const float* bih   = (const float*)d_in[5];
    const float* bhh   = (const float*)d_in[6];

    float* out         = (float*)d_out;
    float* out_outputs = out;
    float* out_cx      = out_outputs + (size_t)TT * BB * HH;
    float* out_evih    = out_cx + (size_t)BB * HH;
    float* out_evhh    = out_evih + (size_t)BB * H3 * II;
    float* out_evb     = out_evhh + (size_t)BB * H3 * HH;

    prep_kernel<<<512, 256>>>(h0, bih, bhh);
    pack_w<<<dim3(II / 32, H4 / 32), dim3(32, 8)>>>(wih, II, 0);
    pack_w<<<dim3(HH / 32, H4 / 32), dim3(32, 8)>>>(whh, HH, 1);
    gx_kernel<<<dim3(16, 50), 256>>>(input);

    loop_kernel<<<NBLK, 256>>>(c0, out_outputs, out_cx);

    scan_kernel<<<BB * H3 / 256, 256>>>(out_evb);
    ev_kernel<<<dim3(II / 128, H3 / 128, BB), 256>>>(input, II, out_evih);
    ev_kernel<<<dim3(HH / 128, H3 / 128, BB), 256>>>(nullptr, HH, out_evhh);
}

// round 9
// speedup vs baseline: 1.8260x; 1.1633x over previous
#include <cuda_runtime.h>
#include <math.h>

#define TT 100
#define BB 64
#define II 256
#define HH 512
#define H3 1536
#define H4 2048
#define NBLK 128          // persistent grid size (all co-resident)
#define KC 8              // K split chunks (512/64)
#define BKC 64            // K per chunk
#define BROW 284          // swizzled B row floats (71 f4 slots, PF4 max 70)
#define AROW 36           // A row floats (32 m + pad, 16B-aligned rows)

// float4-index permutation: conflict-free per quarter-warp for stride-2 and stride-1 patterns
#define PF4(x) ((x) + ((x) >> 3))

// ---------------- scratch (device globals) ----------------
__device__ float g_WihP[II * H4];                 // packed: [k][ (n%512)*4 + n/512 ]
__device__ float g_WhhP[HH * H4];
__device__ float g_biasP[H4];
__device__ float g_Gx[(size_t)TT * BB * H4];      // packed gate pre-activations from input path
__device__ float g_h[(size_t)(TT + 1) * BB * HH]; // h history [t][b][h]
__device__ float g_f[(size_t)TT * BB * HH];
__device__ float g_d[(size_t)TT * BB * H3];       // later overwritten with w = d * suffix-prod(f)
__device__ float g_gpart[16 * 32 * H4];           // split-K partials [kcmh][m-local][packed n]
__device__ unsigned g_cnt_g[TT][8];               // partials-done counters per (t, nt)
__device__ unsigned g_cnt_c[TT][8];               // cells-done counters per (t, nt)

// ---------------- prep ----------------
__global__ void prep_kernel(const float* __restrict__ h0, const float* __restrict__ bih,
                            const float* __restrict__ bhh) {
    int i = blockIdx.x * blockDim.x + threadIdx.x;
    if (i < TT * 8) { (&g_cnt_g[0][0])[i] = 0u; (&g_cnt_c[0][0])[i] = 0u; }
    if (i < H4) g_biasP[(i & 511) * 4 + (i >> 9)] = bih[i] + bhh[i];
    if (i < BB * HH) g_h[i] = h0[i];
}

// ---------------- pack weights: in[2048][K] -> out[K][2048 packed] ----------------
__global__ void pack_w(const float* __restrict__ in, int K, int which) {
    __shared__ float s[32][33];
    int k0 = blockIdx.x * 32, n0 = blockIdx.y * 32;
    int tx = threadIdx.x, ty = threadIdx.y;
    for (int i = ty; i < 32; i += 8)
        s[i][tx] = in[(size_t)(n0 + i) * K + k0 + tx];
    __syncthreads();
    float* out = which ? g_WhhP : g_WihP;
    int g = n0 >> 9;
    int c = n0 & 511;
    for (int i = ty; i < 32; i += 8)
        out[(size_t)(k0 + i) * H4 + (c + tx) * 4 + g] = s[tx][i];
}

// ---------------- Gx = X[6400,256] @ WihP + biasP (packed out) — R6 scalar version ----------------
__global__ void gx_kernel(const float* __restrict__ X) {
    __shared__ __align__(16) float As[8][132];
    __shared__ __align__(16) float Bs[8][140];
    const int tid = threadIdx.x;
    const int n0 = blockIdx.x * 128;
    const int m0 = blockIdx.y * 128;
    const int tm = (tid >> 4) * 8, tn = (tid & 15) * 8;
    const int am = tid >> 1, ak = (tid & 1) * 4;
    const int bk = tid >> 5, bn_f4 = tid & 31;
    const int pn0 = PF4((tn >> 2));
    const int pn1 = PF4((tn >> 2) + 1);
    float acc[8][8] = {};
    for (int k0 = 0; k0 < II; k0 += 8) {
        float4 av = *(const float4*)(X + (size_t)(m0 + am) * II + k0 + ak);
        As[ak + 0][am] = av.x; As[ak + 1][am] = av.y; As[ak + 2][am] = av.z; As[ak + 3][am] = av.w;
        ((float4*)&Bs[bk][0])[PF4(bn_f4)] = *(const float4*)(g_WihP + (size_t)(k0 + bk) * H4 + n0 + bn_f4 * 4);
        __syncthreads();
#pragma unroll
        for (int u = 0; u < 8; u++) {
            float4 a0 = *(const float4*)&As[u][tm];
            float4 a1 = *(const float4*)&As[u][tm + 4];
            float4 b0 = ((const float4*)&Bs[u][0])[pn0];
            float4 b1 = ((const float4*)&Bs[u][0])[pn1];
            float aa[8] = {a0.x, a0.y, a0.z, a0.w, a1.x, a1.y, a1.z, a1.w};
            float bb[8] = {b0.x, b0.y, b0.z, b0.w, b1.x, b1.y, b1.z, b1.w};
#pragma unroll
            for (int i = 0; i < 8; i++)
#pragma unroll
                for (int j = 0; j < 8; j++)
                    acc[i][j] += aa[i] * bb[j];
        }
        __syncthreads();
    }
#pragma unroll
    for (int i = 0; i < 8; i++) {
        float* orow = g_Gx + (size_t)(m0 + tm + i) * H4 + n0 + tn;
        float4 v0 = make_float4(acc[i][0] + g_biasP[n0 + tn + 0], acc[i][1] + g_biasP[n0 + tn + 1],
                                acc[i][2] + g_biasP[n0 + tn + 2], acc[i][3] + g_biasP[n0 + tn + 3]);
        float4 v1 = make_float4(acc[i][4] + g_biasP[n0 + tn + 4], acc[i][5] + g_biasP[n0 + tn + 5],
                                acc[i][6] + g_biasP[n0 + tn + 6], acc[i][7] + g_biasP[n0 + tn + 7]);
        *(float4*)orow = v0;
        *(float4*)(orow + 4) = v1;
    }
}

// ---------------- persistent recurrent loop: flag-pipelined split-K (KC=8, M-split 2) ----------------
// 128 blocks x 256 threads. Block (nt 0..7, kc 0..7, mh 0..1):
//   GEMM tile M=32 (batch rows mh*32..+32), N=256 packed (nt), K=64 (kc).
//   Warp-uniform m -> A reads are LDS broadcasts; per-u mix = 32 FFMA + 3 LDS.
// Cell: block handles b in [kcmh*4, +4) x h-cols [nt*64, +64); c state in register.
__global__ void __launch_bounds__(256, 1)
loop_kernel(const float* __restrict__ c0, float* __restrict__ out_h, float* __restrict__ out_c) {
    extern __shared__ float smdyn[];
    float* Bsm = smdyn;                  // [64][BROW]  (~72.7 KB)
    float* Asm = smdyn + 64 * BROW;      // [64][AROW]  (~9.2 KB)

    const int tid = threadIdx.x;
    const int nt = blockIdx.x & 7;
    const int kcmh = blockIdx.x >> 3;    // 0..15
    const int kc = kcmh >> 1;            // 0..7
    const int mh = kcmh & 1;             // 0..1
    const int n0 = nt * 256;
    const int k0 = kc * BKC;
    const int m0 = mh * 32;

    // stage weight chunk once (swizzled): 64k x 64 f4
    {
        const float* wsrc = g_WhhP + (size_t)k0 * H4 + n0;
#pragma unroll
        for (int r = 0; r < 16; r++) {
            int e = r * 256 + tid;
            int kk = e >> 6;
            int nf4 = e & 63;
            ((float4*)(Bsm + kk * BROW))[PF4(nf4)] = *(const float4*)(wsrc + (size_t)kk * H4 + nf4 * 4);
        }
    }

    const int tm = (tid >> 5) * 4;           // warp-uniform m (broadcast A reads), 0..28
    const int tn = (tid & 31) * 8;
    const int pn0 = PF4(tn >> 2);
    const int pn1 = PF4((tn >> 2) + 1);
    const int am = tid >> 3, ak = (tid & 7) * 8;   // A load map: 32 m rows x 8 k-octs

    // cell identity (fixed all steps)
    const int cb = kcmh * 4 + (tid >> 6);    // batch
    const int ch = nt * 64 + (tid & 63);     // global h col
    float creg = c0[(size_t)cb * HH + ch];

    for (int t = 0; t < TT; t++) {
        // ---- wait for h[t] producers (skip t=0: prep wrote it). nt_src = kc. ----
        if (t > 0) {
            if (tid == 0) {
                volatile unsigned* p = &g_cnt_c[t - 1][kc];
                while (*p < 16u) __nanosleep(64);
                __threadfence();
            }
            __syncthreads();
        }

        // ---- load A chunk: h[t][m0..m0+32)[k0..k0+64) -> Asm[k][m] ----
        const float* hsrc = g_h + (size_t)t * BB * HH;
        float4 v0 = __ldcg((const float4*)(hsrc + (size_t)(m0 + am) * HH + k0 + ak));
        float4 v1 = __ldcg((const float4*)(hsrc + (size_t)(m0 + am) * HH + k0 + ak + 4));
        Asm[(ak + 0) * AROW + am] = v0.x; Asm[(ak + 1) * AROW + am] = v0.y;
        Asm[(ak + 2) * AROW + am] = v0.z; Asm[(ak + 3) * AROW + am] = v0.w;
        Asm[(ak + 4) * AROW + am] = v1.x; Asm[(ak + 5) * AROW + am] = v1.y;
        Asm[(ak + 6) * AROW + am] = v1.z; Asm[(ak + 7) * AROW + am] = v1.w;
        __syncthreads();

        // ---- GEMM 32x256, K=64 ----
        float acc[4][8] = {};
#pragma unroll 16
        for (int u = 0; u < BKC; u++) {
            float4 a = *(const float4*)(Asm + u * AROW + tm);   // broadcast
            float4 b0 = ((const float4*)(Bsm + u * BROW))[pn0];
            float4 b1 = ((const float4*)(Bsm + u * BROW))[pn1];
            float aa[4] = {a.x, a.y, a.z, a.w};
            float bb[8] = {b0.x, b0.y, b0.z, b0.w, b1.x, b1.y, b1.z, b1.w};
#pragma unroll
            for (int i = 0; i < 4; i++)
#pragma unroll
                for (int j = 0; j < 8; j++)
                    acc[i][j] += aa[i] * bb[j];
        }
#pragma unroll
        for (int i = 0; i < 4; i++) {
            float* prow = g_gpart + ((size_t)kcmh * 32 + tm + i) * H4 + n0 + tn;
            *(float4*)prow = make_float4(acc[i][0], acc[i][1], acc[i][2], acc[i][3]);
            *(float4*)(prow + 4) = make_float4(acc[i][4], acc[i][5], acc[i][6], acc[i][7]);
        }

        // ---- signal partials done, wait for all 16 producers of our nt ----
        __threadfence();
        __syncthreads();                      // Asm also reused next step
        if (tid == 0) {
            atomicAdd(&g_cnt_g[t][nt], 1u);
            volatile unsigned* p = &g_cnt_g[t][nt];
            while (*p < 16u) __nanosleep(64);
            __threadfence();
        }
        __syncthreads();

        // ---- cell for (cb, ch): sum 8 partials (kc 0..7, mh = cb>>5) ----
        {
            float4 g4 = __ldcg((const float4*)(g_Gx + ((size_t)t * BB + cb) * H4 + 4 * ch));
            const int mrow = ((cb >> 5) * 32 + (cb & 31));   // [mh][m-local] -> but indexed per kcmh below
#pragma unroll
            for (int q = 0; q < KC; q++) {
                int pk = q * 2 + (cb >> 5);
                float4 p = __ldcg((const float4*)(g_gpart + ((size_t)pk * 32 + (cb & 31)) * H4 + 4 * ch));
                g4.x += p.x; g4.y += p.y; g4.z += p.z; g4.w += p.w;
            }
            (void)mrow;
            float i = 1.f / (1.f + expf(-g4.x));
            float f = 1.f / (1.f + expf(-g4.y));
            float g = tanhf(g4.z);
            float o = 1.f / (1.f + expf(-g4.w));
            float cx = creg;
            float cy = f * cx + i * g;
            float hy = o * tanhf(cy);
            creg = cy;
            size_t hb = (size_t)cb * HH + ch;
            g_h[(size_t)(t + 1) * BB * HH + hb] = hy;
            out_h[(size_t)t * BB * HH + hb] = hy;
            g_f[(size_t)t * BB * HH + hb] = f;
            size_t db = (size_t)t * BB * H3 + (size_t)cb * H3 + ch;
            g_d[db]          = g * i * (1.f - i);
            g_d[db + HH]     = cx * f * (1.f - f);
            g_d[db + 2 * HH] = i * (1.f - g) * (1.f + g);
            if (t == TT - 1) out_c[hb] = cy;
        }

        // ---- signal cells done ----
        __threadfence();
        __syncthreads();
        if (tid == 0) atomicAdd(&g_cnt_c[t][nt], 1u);
    }
}

// ---------------- reverse suffix-product scan ----------------
__global__ void scan_kernel(float* __restrict__ evb_out) {
    int idx = blockIdx.x * blockDim.x + threadIdx.x;  // < BB*H3
    int b = idx / H3, j = idx % H3;
    int h = j & (HH - 1);
    float p = 1.f, sum = 0.f;
    for (int t = TT - 1; t >= 0; t--) {
        size_t di = (size_t)t * BB * H3 + (size_t)b * H3 + j;
        float w = g_d[di] * p;
        g_d[di] = w;
        sum += w;
        p *= g_f[(size_t)t * BB * HH + (size_t)b * HH + h];
    }
    evb_out[idx] = sum;
}

// ---------------- batched ev GEMM: out[b][j][k] = sum_t w[t][b][j] * Xs[t][b][k] ----------------
// 128x128 tile, 256 threads, acc[16][4]: tj warp-uniform -> A reads broadcast; 1 B LDS per 64 FMA.
__global__ void __launch_bounds__(256, 2)
ev_kernel(const float* __restrict__ Xs, int kdim, float* __restrict__ out) {
    __shared__ __align__(16) float Ws[8][132];
    __shared__ __align__(16) float Bs[8][140];
    if (Xs == nullptr) Xs = g_h;  // ev_hh: h_{t-1} history
    const int tid = threadIdx.x;
    const int b = blockIdx.z;
    const int j0 = blockIdx.y * 128;
    const int k0 = blockIdx.x * 128;
    const int tj = (tid >> 5) * 16;          // warp-uniform j base
    const int tk = (tid & 31) * 4;
    const int pk = PF4(tk >> 2);
    const int ltt = tid >> 5;
    const int lc = tid & 31;
    float acc[16][4] = {};
    for (int t0 = 0; t0 < TT; t0 += 8) {
        int t = t0 + ltt;
        float4 wv = make_float4(0.f, 0.f, 0.f, 0.f);
        float4 xv = make_float4(0.f, 0.f, 0.f, 0.f);
        if (t < TT) {
            wv = *(const float4*)(g_d + (size_t)t * BB * H3 + (size_t)b * H3 + j0 + lc * 4);
            xv = *(const float4*)(Xs + ((size_t)t * BB + b) * kdim + k0 + lc * 4);
        }
        *(float4*)&Ws[ltt][lc * 4] = wv;
        ((float4*)&Bs[ltt][0])[PF4(lc)] = xv;
        __syncthreads();
#pragma unroll
        for (int u = 0; u < 8; u++) {
            float4 a0 = *(const float4*)&Ws[u][tj];        // broadcasts
            float4 a1 = *(const float4*)&Ws[u][tj + 4];
            float4 a2 = *(const float4*)&Ws[u][tj + 8];
            float4 a3 = *(const float4*)&Ws[u][tj + 12];
            float4 bv = ((const float4*)&Bs[u][0])[pk];
            float aa[16] = {a0.x, a0.y, a0.z, a0.w, a1.x, a1.y, a1.z, a1.w,
                            a2.x, a2.y, a2.z, a2.w, a3.x, a3.y, a3.z, a3.w};
#pragma unroll
            for (int i = 0; i < 16; i++) {
                acc[i][0] += aa[i] * bv.x;
                acc[i][1] += aa[i] * bv.y;
                acc[i][2] += aa[i] * bv.z;
                acc[i][3] += aa[i] * bv.w;
            }
        }
        __syncthreads();
    }
#pragma unroll
    for (int i = 0; i < 16; i++) {
        float* orow = out + ((size_t)b * H3 + j0 + tj + i) * kdim + k0 + tk;
        *(float4*)orow = make_float4(acc[i][0], acc[i][1], acc[i][2], acc[i][3]);
    }
}

// ---------------- launch ----------------
extern "C" void kernel_launch(void* const* d_in, const int* in_sizes, int n_in,
                              void* d_out, int out_size) {
    (void)in_sizes; (void)n_in; (void)out_size;
    const float* input = (const float*)d_in[0];
    const float* h0    = (const float*)d_in[1];
    const float* c0    = (const float*)d_in[2];
    const float* wih   = (const float*)d_in[3];
    const float* whh   = (const float*)d_in[4];
    const float* bih   = (const float*)d_in[5];
    const float* bhh   = (const float*)d_in[6];

    float* out         = (float*)d_out;
    float* out_outputs = out;
    float* out_cx      = out_outputs + (size_t)TT * BB * HH;
    float* out_evih    = out_cx + (size_t)BB * HH;
    float* out_evhh    = out_evih + (size_t)BB * H3 * II;
    float* out_evb     = out_evhh + (size_t)BB * H3 * HH;

    const int loop_smem = (64 * BROW + 64 * AROW) * 4;   // ~82 KB
    cudaFuncSetAttribute(loop_kernel, cudaFuncAttributeMaxDynamicSharedMemorySize, loop_smem);

    prep_kernel<<<512, 256>>>(h0, bih, bhh);
    pack_w<<<dim3(II / 32, H4 / 32), dim3(32, 8)>>>(wih, II, 0);
    pack_w<<<dim3(HH / 32, H4 / 32), dim3(32, 8)>>>(whh, HH, 1);
    gx_kernel<<<dim3(16, 50), 256>>>(input);

    loop_kernel<<<NBLK, 256, loop_smem>>>(c0, out_outputs, out_cx);

    scan_kernel<<<BB * H3 / 256, 256>>>(out_evb);
    ev_kernel<<<dim3(II / 128, H3 / 128, BB), 256>>>(input, II, out_evih);
    ev_kernel<<<dim3(HH / 128, H3 / 128, BB), 256>>>(nullptr, HH, out_evhh);
}